// round 13
// baseline (speedup 1.0000x reference)
#include <cuda_runtime.h>

// Gray-Scott residual: y-march, z-pair/thread, 8 y outputs/thread.
// 5-deep float2 register ring of center rows per channel (y-taps free),
// z-window edges via warp shuffle, float2 loads, single marching pointer.
// R13 = R12 with __launch_bounds__(256,7): 7 blocks/SM, reg cap 36.
// Input: output (50,2,100,100,100) fp32. Output: f_u(48,96,96,96) ++ f_v.

#define TOUT 48
#define D 96
#define IN_T 2000000
#define IN_C 1000000
#define IN_Y 10000
#define IN_X 100
#define N_OUT (TOUT * D * D * D)       // 42467328
#define YM 8                           // y outputs per thread
#define NTHREADS (N_OUT / (2 * YM))    // 2654208

__device__ __forceinline__ float2 ldg2(const float* p) {
    return __ldg((const float2*)p);
}
__device__ __forceinline__ float2 shup(float2 v) {
    float2 r;
    r.x = __shfl_up_sync(0xffffffffu, v.x, 1);
    r.y = __shfl_up_sync(0xffffffffu, v.y, 1);
    return r;
}
__device__ __forceinline__ float2 shdn(float2 v) {
    float2 r;
    r.x = __shfl_down_sync(0xffffffffu, v.x, 1);
    r.y = __shfl_down_sync(0xffffffffu, v.y, 1);
    return r;
}

__global__ void __launch_bounds__(256, 7) gs13(
    const float* __restrict__ in, float* __restrict__ out)
{
    int idx = blockIdx.x * 256 + threadIdx.x;
    if (idx >= NTHREADS) return;

    int zp = idx % 48;  int q = idx / 48;
    int x  = q % D;     q /= D;
    int yb = q % (D / YM);
    int t  = q / (D / YM);

    const unsigned lane = threadIdx.x & 31u;
    const bool hu = (lane > 0)  && (zp > 0);
    const bool hd = (lane < 31) && (zp < 47);

    // marching center-row pointer: (t, u, y_in = y0+2, x+2, 2zp+2)
    const float* pc = in + t * IN_T + (yb * YM + 2) * IN_Y
                    + (x + 2) * IN_X + (2 * zp + 2);
    float* ob = out + ((t * D + yb * YM) * D + x) * D + 2 * zp;

    const float INV_DX2 = 2304.0f / 10000.0f;
    const float C1 = 4.0f / 3.0f;
    const float C2 = -1.0f / 12.0f;
    const float C0 = -7.5f;

    // register rings: center rows (ring idx 2 = current center)
    float2 ru[5], rv[5];
    ru[0] = ldg2(pc - 2 * IN_Y); rv[0] = ldg2(pc + IN_C - 2 * IN_Y);
    ru[1] = ldg2(pc - IN_Y);     rv[1] = ldg2(pc + IN_C - IN_Y);
    ru[2] = ldg2(pc);            rv[2] = ldg2(pc + IN_C);
    ru[3] = ldg2(pc + IN_Y);     rv[3] = ldg2(pc + IN_C + IN_Y);

    #pragma unroll
    for (int k = 0; k < YM; k++) {
        // ring refill (row y_in = y+4)
        ru[4] = ldg2(pc + 2 * IN_Y);
        rv[4] = ldg2(pc + IN_C + 2 * IN_Y);

        // x-taps (center row)
        float2 uxm1 = ldg2(pc - IN_X),            uxp1 = ldg2(pc + IN_X);
        float2 uxm2 = ldg2(pc - 2 * IN_X),        uxp2 = ldg2(pc + 2 * IN_X);
        float2 vxm1 = ldg2(pc + IN_C - IN_X),     vxp1 = ldg2(pc + IN_C + IN_X);
        float2 vxm2 = ldg2(pc + IN_C - 2 * IN_X), vxp2 = ldg2(pc + IN_C + 2 * IN_X);

        // t+1 centers (same spatial spot, next time slice)
        float2 un = ldg2(pc + IN_T);
        float2 vn = ldg2(pc + IN_T + IN_C);

        // z-window edges via shuffle (boundary fallback)
        float2 cu = ru[2], cv = rv[2];
        float2 uwl = shup(cu), uwr = shdn(cu);
        float2 vwl = shup(cv), vwr = shdn(cv);
        if (!hu) { uwl = ldg2(pc - 2); vwl = ldg2(pc + IN_C - 2); }
        if (!hd) { uwr = ldg2(pc + 2); vwr = ldg2(pc + IN_C + 2); }

        float s1ux = uwl.y + cu.y + uxm1.x + uxp1.x + ru[1].x + ru[3].x;
        float s2ux = uwl.x + uwr.x + uxm2.x + uxp2.x + ru[0].x + ru[4].x;
        float s1uy = cu.x + uwr.x + uxm1.y + uxp1.y + ru[1].y + ru[3].y;
        float s2uy = uwl.y + uwr.y + uxm2.y + uxp2.y + ru[0].y + ru[4].y;

        float s1vx = vwl.y + cv.y + vxm1.x + vxp1.x + rv[1].x + rv[3].x;
        float s2vx = vwl.x + vwr.x + vxm2.x + vxp2.x + rv[0].x + rv[4].x;
        float s1vy = cv.x + vwr.x + vxm1.y + vxp1.y + rv[1].y + rv[3].y;
        float s2vy = vwl.y + vwr.y + vxm2.y + vxp2.y + rv[0].y + rv[4].y;

        float lapux = (C0 * cu.x + C1 * s1ux + C2 * s2ux) * INV_DX2;
        float lapuy = (C0 * cu.y + C1 * s1uy + C2 * s2uy) * INV_DX2;
        float lapvx = (C0 * cv.x + C1 * s1vx + C2 * s2vx) * INV_DX2;
        float lapvy = (C0 * cv.y + C1 * s1vy + C2 * s2vy) * INV_DX2;

        float uv2x = cu.x * cv.x * cv.x;
        float uv2y = cu.y * cv.y * cv.y;

        float2 fu, fv;
        fu.x = 0.2f * lapux - uv2x + 0.025f * (1.0f - cu.x) - (un.x - cu.x) * 2.0f;
        fu.y = 0.2f * lapuy - uv2y + 0.025f * (1.0f - cu.y) - (un.y - cu.y) * 2.0f;
        fv.x = 0.1f * lapvx + uv2x - 0.08f * cv.x - (vn.x - cv.x) * 2.0f;
        fv.y = 0.1f * lapvy + uv2y - 0.08f * cv.y - (vn.y - cv.y) * 2.0f;

        *(float2*)ob           = fu;
        *(float2*)(ob + N_OUT) = fv;

        // rotate rings, advance pointers
        #pragma unroll
        for (int m = 0; m < 4; m++) { ru[m] = ru[m + 1]; rv[m] = rv[m + 1]; }
        pc += IN_Y;
        ob += D * D;
    }
}

extern "C" void kernel_launch(void* const* d_in, const int* in_sizes, int n_in,
                              void* d_out, int out_size)
{
    const float* in = (const float*)d_in[0];
    float* out = (float*)d_out;
    int blocks = (NTHREADS + 255) / 256;   // 10368
    gs13<<<blocks, 256>>>(in, out);
}

// round 14
// speedup vs baseline: 1.1528x; 1.1528x over previous
#include <cuda_runtime.h>

// Gray-Scott residual: 8 outputs/thread (z-pair x x-pair x y-pair),
// float2 loads, z-edges via warp shuffle, taps shared across x and y pairs.
// R14 = R9 + __launch_bounds__(256,5): reg cap 51 -> 5 blocks/SM (was 52 -> 4).
// Input: output (50,2,100,100,100) fp32. Output: f_u(48,96,96,96) ++ f_v.

#define TOUT 48
#define D 96
#define IN_T 2000000
#define IN_C 1000000
#define IN_Y 10000
#define IN_X 100
#define N_OUT (TOUT * D * D * D)       // 42467328
#define NTHREADS (N_OUT / 8)           // 5308416

__device__ __forceinline__ float2 ldg2(const float* p) {
    return __ldg((const float2*)p);
}
__device__ __forceinline__ float2 shup(float2 v) {
    float2 r;
    r.x = __shfl_up_sync(0xffffffffu, v.x, 1);
    r.y = __shfl_up_sync(0xffffffffu, v.y, 1);
    return r;
}
__device__ __forceinline__ float2 shdn(float2 v) {
    float2 r;
    r.x = __shfl_down_sync(0xffffffffu, v.x, 1);
    r.y = __shfl_down_sync(0xffffffffu, v.y, 1);
    return r;
}

__global__ void __launch_bounds__(256, 5) gs14(
    const float* __restrict__ in, float* __restrict__ out)
{
    int idx = blockIdx.x * 256 + threadIdx.x;
    if (idx >= NTHREADS) return;

    int zp = idx % 48;  int q = idx / 48;
    int xp = q % 48;    q /= 48;
    int yp = q % 48;    int t = q / 48;

    const int zi = 2 * zp, xi = 2 * xp, yi = 2 * yp;

    // center point (r=0, xr=0): input (t, ch, yi+2, xi+2, zi+2)
    const float* P = in + t * IN_T + (yi + 2) * IN_Y + (xi + 2) * IN_X + (zi + 2);

    const unsigned lane = threadIdx.x & 31u;
    const bool hu = (lane > 0)  && (zp > 0);
    const bool hd = (lane < 31) && (zp < 47);

    const float INV_DX2 = 2304.0f / 10000.0f;
    const float C1 = 4.0f / 3.0f;
    const float C2 = -1.0f / 12.0f;
    const float C0 = -7.5f;

    // carried u-pass results: centers + partial f_u for 8 points
    float2 cu[2][2], pu[2][2];

    #pragma unroll
    for (int ch = 0; ch < 2; ch++) {
        const float* p = P + ch * IN_C;

        // centers: [y-row r][x-row xr]
        float2 c[2][2];
        c[0][0] = ldg2(p);
        c[0][1] = ldg2(p + IN_X);
        c[1][0] = ldg2(p + IN_Y);
        c[1][1] = ldg2(p + IN_Y + IN_X);

        // z-window edges via shuffle; boundary fallback loads
        float2 wl[2][2], wr[2][2];
        #pragma unroll
        for (int r = 0; r < 2; r++)
            #pragma unroll
            for (int xr = 0; xr < 2; xr++) {
                wl[r][xr] = shup(c[r][xr]);
                wr[r][xr] = shdn(c[r][xr]);
            }
        if (!hu) {
            wl[0][0] = ldg2(p - 2);
            wl[0][1] = ldg2(p + IN_X - 2);
            wl[1][0] = ldg2(p + IN_Y - 2);
            wl[1][1] = ldg2(p + IN_Y + IN_X - 2);
        }
        if (!hd) {
            wr[0][0] = ldg2(p + 2);
            wr[0][1] = ldg2(p + IN_X + 2);
            wr[1][0] = ldg2(p + IN_Y + 2);
            wr[1][1] = ldg2(p + IN_Y + IN_X + 2);
        }

        // x-taps per y-row: tap-only rows x = xi, xi+1, xi+4, xi+5
        float2 Xt[2][4];
        #pragma unroll
        for (int r = 0; r < 2; r++) {
            const float* pr = p + r * IN_Y;
            Xt[r][0] = ldg2(pr - 2 * IN_X);
            Xt[r][1] = ldg2(pr - IN_X);
            Xt[r][2] = ldg2(pr + 2 * IN_X);
            Xt[r][3] = ldg2(pr + 3 * IN_X);
        }

        // y-taps per x-row: tap-only rows y = yi, yi+1, yi+4, yi+5
        float2 Yt[2][4];
        #pragma unroll
        for (int xr = 0; xr < 2; xr++) {
            const float* pr = p + xr * IN_X;
            Yt[xr][0] = ldg2(pr - 2 * IN_Y);
            Yt[xr][1] = ldg2(pr - IN_Y);
            Yt[xr][2] = ldg2(pr + 2 * IN_Y);
            Yt[xr][3] = ldg2(pr + 3 * IN_Y);
        }

        // t+1 centers
        float2 nx[2][2];
        nx[0][0] = ldg2(p + IN_T);
        nx[0][1] = ldg2(p + IN_T + IN_X);
        nx[1][0] = ldg2(p + IN_T + IN_Y);
        nx[1][1] = ldg2(p + IN_T + IN_Y + IN_X);

        #pragma unroll
        for (int r = 0; r < 2; r++) {
            #pragma unroll
            for (int xr = 0; xr < 2; xr++) {
                float2 cc = c[r][xr];
                float2 l = wl[r][xr], w = wr[r][xr];

                float2 xm1 = (xr == 0) ? Xt[r][1] : c[r][0];
                float2 xq1 = (xr == 0) ? c[r][1]  : Xt[r][2];
                float2 xm2 = (xr == 0) ? Xt[r][0] : Xt[r][1];
                float2 xq2 = (xr == 0) ? Xt[r][2] : Xt[r][3];

                float2 ym1 = (r == 0) ? Yt[xr][1] : c[0][xr];
                float2 yq1 = (r == 0) ? c[1][xr]  : Yt[xr][2];
                float2 ym2 = (r == 0) ? Yt[xr][0] : Yt[xr][1];
                float2 yq2 = (r == 0) ? Yt[xr][2] : Yt[xr][3];

                float s1x = l.y + cc.y + xm1.x + xq1.x + ym1.x + yq1.x;
                float s2x = l.x + w.x + xm2.x + xq2.x + ym2.x + yq2.x;
                float s1y = cc.x + w.x + xm1.y + xq1.y + ym1.y + yq1.y;
                float s2y = l.y + w.y + xm2.y + xq2.y + ym2.y + yq2.y;

                float lapx = (C0 * cc.x + C1 * s1x + C2 * s2x) * INV_DX2;
                float lapy = (C0 * cc.y + C1 * s1y + C2 * s2y) * INV_DX2;
                float2 n = nx[r][xr];

                if (ch == 0) {
                    cu[r][xr] = cc;
                    pu[r][xr].x = 0.2f * lapx + 0.025f * (1.0f - cc.x)
                                - (n.x - cc.x) * 2.0f;
                    pu[r][xr].y = 0.2f * lapy + 0.025f * (1.0f - cc.y)
                                - (n.y - cc.y) * 2.0f;
                } else {
                    float uvx = cu[r][xr].x * cc.x * cc.x;
                    float uvy = cu[r][xr].y * cc.y * cc.y;
                    float2 fu, fv;
                    fu.x = pu[r][xr].x - uvx;
                    fu.y = pu[r][xr].y - uvy;
                    fv.x = 0.1f * lapx + uvx - 0.08f * cc.x - (n.x - cc.x) * 2.0f;
                    fv.y = 0.1f * lapy + uvy - 0.08f * cc.y - (n.y - cc.y) * 2.0f;

                    int o = ((t * D + yi + r) * D + xi + xr) * D + zi;
                    *(float2*)(out + o)         = fu;
                    *(float2*)(out + o + N_OUT) = fv;
                }
            }
        }
    }
}

extern "C" void kernel_launch(void* const* d_in, const int* in_sizes, int n_in,
                              void* d_out, int out_size)
{
    const float* in = (const float*)d_in[0];
    float* out = (float*)d_out;
    int blocks = (NTHREADS + 255) / 256;   // 20736
    gs14<<<blocks, 256>>>(in, out);
}